// round 4
// baseline (speedup 1.0000x reference)
#include <cuda_runtime.h>

#define NN 100000
#define EE 1600000
#define DDIM 8
#define HDIM 256

// ---- node data ----
__device__ float4 g_qn  [NN*2];   // q * norm_src
__device__ float4 g_md4 [NN*2];
__device__ float4 g_agg1[NN*2];
__device__ float4 g_vn  [NN*2];   // v * norm_src
__device__ float4 g_h2  [NN*2];
__device__ float4 g_G   [NN*2];
__device__ float4 g_Gn  [NN*2];   // G * norm_dst
__device__ float4 g_r   [NN*2];
__device__ float4 g_zzn [NN*2];   // zz * norm_dst
__device__ float  g_norm_src[NN];
__device__ float  g_norm_dst[NN];
__device__ unsigned g_mask[NN*DDIM];
// ---- CSR ----
__device__ int   g_degout[NN], g_degin[NN];
__device__ int   g_rowQ[NN], g_rowS[NN];     // row starts (in-CSR / out-CSR)
__device__ int   g_curQ[NN], g_curS[NN];     // fill cursors
__device__ int   g_colQ[EE];                 // in-CSR: src per in-edge of node
__device__ int   g_colS[EE];                 // out-CSR: dst per out-edge of node
__device__ int   g_posQ[EE], g_posS[EE];     // slot of original edge e in each CSR
__device__ float g_cQ[EE], g_cS[EE];         // force coefficient per CSR slot
__device__ int   g_ctrQ, g_ctrS;

__device__ __forceinline__ float4 f4add(float4 a, float4 b) {
    return make_float4(a.x+b.x, a.y+b.y, a.z+b.z, a.w+b.w);
}
__device__ __forceinline__ float4 f4scale(float4 a, float s) {
    return make_float4(a.x*s, a.y*s, a.z*s, a.w*s);
}

__global__ void k_init(int n) {
    int i = blockIdx.x * blockDim.x + threadIdx.x;
    if (i < n) { g_degout[i] = 0; g_degin[i] = 0; }
    if (i == 0) { g_ctrQ = 0; g_ctrS = 0; }
}

__global__ void k_deg(const int* __restrict__ src, const int* __restrict__ dst, int E) {
    int e = blockIdx.x * blockDim.x + threadIdx.x;
    if (e >= E) return;
    atomicAdd(&g_degout[src[e]], 1);
    atomicAdd(&g_degin [dst[e]], 1);
}

// norms, CSR row allocation (warp-scan + warp-aggregated bump), md, qn, dHdP
__global__ void k_prep(const float* __restrict__ p, const float* __restrict__ M,
                       const float* __restrict__ q, float4* __restrict__ out4, int n) {
    int nd = blockIdx.x * blockDim.x + threadIdx.x;
    int lane = threadIdx.x & 31;
    bool act = nd < n;
    int din  = act ? g_degin[nd]  : 0;
    int dout = act ? g_degout[nd] : 0;
    int sin = din, sout = dout;
#pragma unroll
    for (int o = 1; o < 32; o <<= 1) {
        int t1 = __shfl_up_sync(0xFFFFFFFFu, sin,  o); if (lane >= o) sin  += t1;
        int t2 = __shfl_up_sync(0xFFFFFFFFu, sout, o); if (lane >= o) sout += t2;
    }
    int baseQ = 0, baseS = 0;
    if (lane == 31) {
        baseQ = atomicAdd(&g_ctrQ, sin);
        baseS = atomicAdd(&g_ctrS, sout);
    }
    baseQ = __shfl_sync(0xFFFFFFFFu, baseQ, 31);
    baseS = __shfl_sync(0xFFFFFFFFu, baseS, 31);
    if (!act) return;
    int rowQ = baseQ + sin - din;
    int rowS = baseS + sout - dout;
    g_rowQ[nd] = rowQ; g_curQ[nd] = rowQ;
    g_rowS[nd] = rowS; g_curS[nd] = rowS;

    float nsrc = (dout > 0) ? rsqrtf((float)dout) : 1.0f;
    float ndst = (din  > 0) ? rsqrtf((float)din)  : 1.0f;
    g_norm_src[nd] = nsrc;
    g_norm_dst[nd] = ndst;
    const float* Mr = M + (long long)nd * 64;
    float md[8];
#pragma unroll
    for (int d = 0; d < 8; d++) md[d] = Mr[d * 9];
    g_md4[nd*2]   = make_float4(md[0], md[1], md[2], md[3]);
    g_md4[nd*2+1] = make_float4(md[4], md[5], md[6], md[7]);
    const float4* q4 = (const float4*)q;
    const float4* p4 = (const float4*)p;
    g_qn[nd*2]   = f4scale(q4[nd*2],   nsrc);
    g_qn[nd*2+1] = f4scale(q4[nd*2+1], nsrc);
    float4 pa = p4[nd*2], pb = p4[nd*2+1];
    out4[nd*4+2] = make_float4(pa.x/md[0], pa.y/md[1], pa.z/md[2], pa.w/md[3]);
    out4[nd*4+3] = make_float4(pb.x/md[4], pb.y/md[5], pb.z/md[6], pb.w/md[7]);
}

// build both CSRs
__global__ void k_fill(const int* __restrict__ src, const int* __restrict__ dst, int E) {
    int e = blockIdx.x * blockDim.x + threadIdx.x;
    if (e >= E) return;
    int s = src[e], u = dst[e];
    int pq = atomicAdd(&g_curQ[u], 1);
    g_colQ[pq] = s;  g_posQ[e] = pq;
    int ps = atomicAdd(&g_curS[s], 1);
    g_colS[ps] = u;  g_posS[e] = ps;
}

// agg1[node] = sum_{in-edges} qn[src]   (2 threads/node, one float4 half each)
__global__ void g_agg1k(int n2) {
    int i = blockIdx.x * blockDim.x + threadIdx.x;
    if (i >= n2) return;
    int node = i >> 1, half = i & 1;
    int start = g_rowQ[node], len = g_degin[node];
    float4 acc = make_float4(0.f, 0.f, 0.f, 0.f);
    for (int k = 0; k < len; k++) {
        int s = __ldg(&g_colQ[start + k]);
        acc = f4add(acc, __ldg(&g_qn[s*2 + half]));
    }
    g_agg1[i] = acc;
}

// forward node MLP (warp per node)
__global__ void k_mlp_fwd(const float* __restrict__ W1v, const float* __restrict__ b1v,
                          const float* __restrict__ W2v, int n) {
    __shared__ float sW1[DDIM * HDIM];
    __shared__ float sW2t[DDIM * HDIM];
    __shared__ float sb1[HDIM];
    int tid = threadIdx.x;
    for (int i = tid; i < DDIM * HDIM; i += 256) {
        sW1[i] = W1v[i];
        int j = i >> 3, d = i & 7;
        sW2t[d * HDIM + j] = W2v[i];
    }
    sb1[tid] = b1v[tid];
    __syncthreads();
    int warp = tid >> 5, lane = tid & 31;
    int node = blockIdx.x * 8 + warp;
    if (node >= n) return;
    float ndst = g_norm_dst[node];
    const float* a1 = (const float*)&g_agg1[node*2];
    float t1[8];
#pragma unroll
    for (int d = 0; d < 8; d++) t1[d] = a1[d] * ndst;
    float acc[8] = {0.f,0.f,0.f,0.f,0.f,0.f,0.f,0.f};
#pragma unroll
    for (int k = 0; k < 8; k++) {
        int j = k * 32 + lane;
        float u = sb1[j];
#pragma unroll
        for (int d = 0; d < 8; d++) u = fmaf(t1[d], sW1[d * HDIM + j], u);
        unsigned m = __ballot_sync(0xFFFFFFFFu, u > 0.f);
        if (lane == 0) g_mask[node * 8 + k] = m;
        float h = (u > 0.f) ? u : 0.f;
#pragma unroll
        for (int d = 0; d < 8; d++) acc[d] = fmaf(h, sW2t[d * HDIM + j], acc[d]);
    }
#pragma unroll
    for (int off = 16; off; off >>= 1)
#pragma unroll
        for (int d = 0; d < 8; d++) acc[d] += __shfl_xor_sync(0xFFFFFFFFu, acc[d], off);
    if (lane == 0) {
        float ns = g_norm_src[node];
        g_vn[node*2]   = make_float4(acc[0]*ns, acc[1]*ns, acc[2]*ns, acc[3]*ns);
        g_vn[node*2+1] = make_float4(acc[4]*ns, acc[5]*ns, acc[6]*ns, acc[7]*ns);
    }
}

// h2[node] = (sum_{in} vn[src]) * ndst + b2 + q   (gather + epilogue fused)
__global__ void g_agg2h2(const float* __restrict__ q, const float* __restrict__ b2, int n2) {
    int i = blockIdx.x * blockDim.x + threadIdx.x;
    if (i >= n2) return;
    int node = i >> 1, half = i & 1;
    int start = g_rowQ[node], len = g_degin[node];
    float4 acc = make_float4(0.f, 0.f, 0.f, 0.f);
    for (int k = 0; k < len; k++) {
        int s = __ldg(&g_colQ[start + k]);
        acc = f4add(acc, __ldg(&g_vn[s*2 + half]));
    }
    float ndst = g_norm_dst[node];
    float4 b2h = ((const float4*)b2)[half];
    float4 qv  = ((const float4*)q)[i];
    g_h2[i] = f4add(f4add(f4scale(acc, ndst), b2h), qv);
}

// per-edge coefficient c; plain stores into both CSR slot arrays
__global__ void k_force_c(const int* __restrict__ src, const int* __restrict__ dst,
                          const float* __restrict__ grav, int E) {
    int e = blockIdx.x * blockDim.x + threadIdx.x;
    if (e >= E) return;
    int s = src[e], u = dst[e];
    float4 hsa = __ldg(&g_h2[s*2]), hsb = __ldg(&g_h2[s*2+1]);
    float4 hua = __ldg(&g_h2[u*2]), hub = __ldg(&g_h2[u*2+1]);
    float4 msa = __ldg(&g_md4[s*2]), msb = __ldg(&g_md4[s*2+1]);
    float4 mua = __ldg(&g_md4[u*2]), mub = __ldg(&g_md4[u*2+1]);
    float dx0 = hsa.x-hua.x, dx1 = hsa.y-hua.y, dx2 = hsa.z-hua.z, dx3 = hsa.w-hua.w;
    float dx4 = hsb.x-hub.x, dx5 = hsb.y-hub.y, dx6 = hsb.z-hub.z, dx7 = hsb.w-hub.w;
    float e2 = dx0*dx0 + dx1*dx1 + dx2*dx2 + dx3*dx3
             + dx4*dx4 + dx5*dx5 + dx6*dx6 + dx7*dx7;
    float sm = msa.x*mua.x + msa.y*mua.y + msa.z*mua.z + msa.w*mua.w
             + msb.x*mub.x + msb.y*mub.y + msb.z*mub.z + msb.w*mub.w;
    float inv = rsqrtf(e2);
    float c = 0.5f * __ldg(grav) * sm * inv * inv * inv;
    g_cQ[__ldg(&g_posQ[e])] = c;
    g_cS[__ldg(&g_posS[e])] = c;
}

// G[n] = sum over in-edges c*(h2[src]-h2[n]) + out-edges c*(h2[dst]-h2[n]); Gn = G*ndst
__global__ void g_Gk(int n2) {
    int i = blockIdx.x * blockDim.x + threadIdx.x;
    if (i >= n2) return;
    int node = i >> 1, half = i & 1;
    float4 h2n = g_h2[i];
    float4 acc = make_float4(0.f, 0.f, 0.f, 0.f);
    int startQ = g_rowQ[node], lenQ = g_degin[node];
    for (int k = 0; k < lenQ; k++) {
        int idx = startQ + k;
        int s = __ldg(&g_colQ[idx]);
        float c = __ldg(&g_cQ[idx]);
        float4 h = __ldg(&g_h2[s*2 + half]);
        acc.x = fmaf(c, h.x - h2n.x, acc.x);
        acc.y = fmaf(c, h.y - h2n.y, acc.y);
        acc.z = fmaf(c, h.z - h2n.z, acc.z);
        acc.w = fmaf(c, h.w - h2n.w, acc.w);
    }
    int startS = g_rowS[node], lenS = g_degout[node];
    for (int k = 0; k < lenS; k++) {
        int idx = startS + k;
        int u = __ldg(&g_colS[idx]);
        float c = __ldg(&g_cS[idx]);
        float4 h = __ldg(&g_h2[u*2 + half]);
        acc.x = fmaf(c, h.x - h2n.x, acc.x);
        acc.y = fmaf(c, h.y - h2n.y, acc.y);
        acc.z = fmaf(c, h.z - h2n.z, acc.z);
        acc.w = fmaf(c, h.w - h2n.w, acc.w);
    }
    g_G[i]  = acc;
    g_Gn[i] = f4scale(acc, g_norm_dst[node]);
}

// r[n] = sum over out-edges Gn[dst]
__global__ void g_rk(int n2) {
    int i = blockIdx.x * blockDim.x + threadIdx.x;
    if (i >= n2) return;
    int node = i >> 1, half = i & 1;
    int start = g_rowS[node], len = g_degout[node];
    float4 acc = make_float4(0.f, 0.f, 0.f, 0.f);
    for (int k = 0; k < len; k++) {
        int u = __ldg(&g_colS[start + k]);
        acc = f4add(acc, __ldg(&g_Gn[u*2 + half]));
    }
    g_r[i] = acc;
}

// backward node MLP
__global__ void k_mlp_bwd(const float* __restrict__ W1v, const float* __restrict__ W2v, int n) {
    __shared__ float sW1[DDIM * HDIM];
    __shared__ float sW2t[DDIM * HDIM];
    int tid = threadIdx.x;
    for (int i = tid; i < DDIM * HDIM; i += 256) {
        sW1[i] = W1v[i];
        int j = i >> 3, d = i & 7;
        sW2t[d * HDIM + j] = W2v[i];
    }
    __syncthreads();
    int warp = tid >> 5, lane = tid & 31;
    int node = blockIdx.x * 8 + warp;
    if (node >= n) return;
    float nsrc = g_norm_src[node];
    const float* rv = (const float*)&g_r[node*2];
    float rr[8];
#pragma unroll
    for (int d = 0; d < 8; d++) rr[d] = rv[d] * nsrc;
    float acc[8] = {0.f,0.f,0.f,0.f,0.f,0.f,0.f,0.f};
#pragma unroll
    for (int k = 0; k < 8; k++) {
        int j = k * 32 + lane;
        float gh = 0.f;
#pragma unroll
        for (int d = 0; d < 8; d++) gh = fmaf(rr[d], sW2t[d * HDIM + j], gh);
        unsigned m = g_mask[node * 8 + k];
        float gu = ((m >> lane) & 1u) ? gh : 0.f;
#pragma unroll
        for (int d = 0; d < 8; d++) acc[d] = fmaf(gu, sW1[d * HDIM + j], acc[d]);
    }
#pragma unroll
    for (int off = 16; off; off >>= 1)
#pragma unroll
        for (int d = 0; d < 8; d++) acc[d] += __shfl_xor_sync(0xFFFFFFFFu, acc[d], off);
    if (lane == 0) {
        float ndst = g_norm_dst[node];
        g_zzn[node*2]   = make_float4(acc[0]*ndst, acc[1]*ndst, acc[2]*ndst, acc[3]*ndst);
        g_zzn[node*2+1] = make_float4(acc[4]*ndst, acc[5]*ndst, acc[6]*ndst, acc[7]*ndst);
    }
}

// w[n] = sum over out-edges zzn[dst]; out = G + nsrc*w  (fused final)
__global__ void g_wfinal(float4* __restrict__ out4, int n2) {
    int i = blockIdx.x * blockDim.x + threadIdx.x;
    if (i >= n2) return;
    int node = i >> 1, half = i & 1;
    int start = g_rowS[node], len = g_degout[node];
    float4 acc = make_float4(0.f, 0.f, 0.f, 0.f);
    for (int k = 0; k < len; k++) {
        int u = __ldg(&g_colS[start + k]);
        acc = f4add(acc, __ldg(&g_zzn[u*2 + half]));
    }
    float ns = g_norm_src[node];
    out4[node*4 + half] = f4add(g_G[i], f4scale(acc, ns));
}

extern "C" void kernel_launch(void* const* d_in, const int* in_sizes, int n_in,
                              void* d_out, int out_size) {
    const float* q    = (const float*)d_in[0];
    const float* p    = (const float*)d_in[1];
    const float* M    = (const float*)d_in[2];
    const int*   src  = (const int*)  d_in[3];
    const int*   dst  = (const int*)  d_in[4];
    const float* W1   = (const float*)d_in[5];
    const float* b1   = (const float*)d_in[6];
    const float* W2   = (const float*)d_in[7];
    const float* b2   = (const float*)d_in[8];
    const float* grav = (const float*)d_in[9];
    float4* out4 = (float4*)d_out;

    int N = in_sizes[0] / DDIM;
    int E = in_sizes[3];
    if (N > NN || E > EE) return;

    int n2 = N * 2;
    int gN  = (N + 255) / 256;
    int gN2 = (n2 + 255) / 256;
    int gE  = (E + 255) / 256;
    int gW  = (N + 7) / 8;

    k_init   <<<gN,  256>>>(N);
    k_deg    <<<gE,  256>>>(src, dst, E);
    k_prep   <<<gN,  256>>>(p, M, q, out4, N);
    k_fill   <<<gE,  256>>>(src, dst, E);
    g_agg1k  <<<gN2, 256>>>(n2);
    k_mlp_fwd<<<gW,  256>>>(W1, b1, W2, N);
    g_agg2h2 <<<gN2, 256>>>(q, b2, n2);
    k_force_c<<<gE,  256>>>(src, dst, grav, E);
    g_Gk     <<<gN2, 256>>>(n2);
    g_rk     <<<gN2, 256>>>(n2);
    k_mlp_bwd<<<gW,  256>>>(W1, W2, N);
    g_wfinal <<<gN2, 256>>>(out4, n2);
}